// round 9
// baseline (speedup 1.0000x reference)
#include <cuda_runtime.h>
#include <cuda_bf16.h>
#include <math.h>

// ---------------------------------------------------------------------------
// DeepDCNN fused: emb-gather -> 4x [conv+fold+ordered-top-k+tanh FUSED] -> FC
// B=64, SEQ=1024, E=64, NC=6
// Layer i: Ghalf=[32,16,8,4], CING=[1,10,14,18], NF=[10,14,18,22],
//          KS=[7,5,5,3], SOUT=SIN+KS-1, KPOOL=[768,512,256,4]
// Fusion: one block = (batch, group-pair, feature-split); conv results stay in
// smem as monotone-flipped keys; per-channel radix-select + stable compaction
// + tanh writes only the pooled rows to HBM. Saves ~300MB/round of traffic.
// ---------------------------------------------------------------------------

__device__ float g_bufB[15728640]; // pooled ping (L0 out 15.73M, L2 out)
__device__ float g_bufC[7340032];  // embed / pooled pong (L1 out 7.34M, L3 out)

// ---------------------------------------------------------------------------
// 1) Embedding gather + transpose via smem: X[b][e][s] = emb[tokens[b][s]][e]
// ---------------------------------------------------------------------------
__global__ __launch_bounds__(256)
void embed_kernel(const int* __restrict__ tokens,
                  const float* __restrict__ emb,
                  float* __restrict__ X)
{
    __shared__ float sm[64 * 65];
    __shared__ int stok[64];
    int blk = blockIdx.x;            // B * 16 blocks
    int b   = blk >> 4;
    int s0  = (blk & 15) << 6;
    int t   = threadIdx.x;

    if (t < 64) stok[t] = tokens[b * 1024 + s0 + t];
    __syncthreads();

    for (int i = t; i < 64 * 16; i += 256) {
        int r  = i >> 4;
        int c4 = i & 15;
        float4 v = *reinterpret_cast<const float4*>(emb + (long long)stok[r] * 64 + c4 * 4);
        float* d = &sm[r * 65 + c4 * 4];
        d[0] = v.x; d[1] = v.y; d[2] = v.z; d[3] = v.w;
    }
    __syncthreads();

    for (int i = t; i < 64 * 64; i += 256) {
        int e = i >> 6, s = i & 63;
        X[((long long)b * 64 + e) * 1024 + s0 + s] = sm[s * 65 + e];
    }
}

__device__ __forceinline__ unsigned flip_key(float f) {
    unsigned u = __float_as_uint(f);
    return (u & 0x80000000u) ? ~u : (u | 0x80000000u);
}

// ---------------------------------------------------------------------------
// 2) FUSED conv+fold+bias -> smem keys -> per-channel ordered top-k + tanh.
//    Conv: packed f32x2 FMA over feature pairs, weights f-innermost in smem
//    (16B aligned -> broadcast LDS.64), x windows via predicated __ldg,
//    SPT=4 consecutive s per thread (R6 form — no reg-heavy prefetch).
//    Kmax: MSB-first radix select w/ warp-aggregated hist + parallel suffix
//    scan; candidate index compaction shrinks refinement passes; stable
//    prefix compaction keeps >T plus first need_eq ==T (lax.top_k ties).
// ---------------------------------------------------------------------------
template<int CING, int NF, int KS, int SIN, int KPOOL, int FSPLIT>
__global__ __launch_bounds__(256)
void conv_kmax_kernel(const float* __restrict__ x, const float* __restrict__ w,
                      const float* __restrict__ bias, float* __restrict__ y,
                      int Ghalf)
{
    constexpr int SOUT  = SIN + KS - 1;
    constexpr int SOUTP = (SOUT + 3) & ~3;          // pad for uint4 stores
    constexpr int NFP   = NF / 2;
    constexpr int FPC   = (NFP + FSPLIT - 1) / FSPLIT;  // fp-pairs per block
    constexpr int SPT   = 4;
    constexpr int WIN   = KS + SPT - 1;
    constexpr int NT    = 256;
    constexpr int PCN   = 2 * CING;
    constexpr int WCNT  = PCN * KS * (2 * FPC);     // smem weight slice floats

    __shared__ __align__(16) unsigned skey[2 * FPC * SOUTP];
    __shared__ __align__(16) float swT[WCNT];       // [p][c][j][fl]
    __shared__ int hist[256];
    __shared__ int warpsum[8];
    __shared__ unsigned short cand[SOUT];
    __shared__ unsigned sh_dig, sh_krem, sh_done, sh_tot;
    __shared__ int sh_ncand;

    int bid = blockIdx.x;
    int fs  = bid % FSPLIT;
    int gp  = (bid / FSPLIT) % Ghalf;
    int b   = bid / (FSPLIT * Ghalf);
    int t   = threadIdx.x;
    int lane = t & 31, wid = t >> 5;

    const int fp0 = fs * FPC;
    const int nfp = min(FPC, NFP - fp0);   // live fp-pairs in this block
    const int CH_IN  = Ghalf * 2 * CING;
    const int CH_OUT = Ghalf * NF;

    // ---- load weight slice, f-local innermost, zero-pad dead features -----
    for (int e = t; e < WCNT; e += NT) {
        int fl = e % (2 * FPC);
        int r  = e / (2 * FPC);
        int j  = r % KS;
        int r2 = r / KS;
        int c  = r2 % CING;
        int p  = r2 / CING;
        float v = 0.f;
        if (fl < 2 * nfp) {
            int gf = 2 * fp0 + fl;
            v = w[((long long)(2 * gp + p) * NF + gf) * CING * KS + c * KS + j];
        }
        swT[((p * CING + c) * KS + j) * (2 * FPC) + fl] = v;
    }
    __syncthreads();

    // ---- conv phase: fill skey with flipped conv+bias values --------------
    const float* xb = x + (long long)b * CH_IN * SIN + (long long)(2 * gp * CING) * SIN;
    for (int s0 = 0; s0 < SOUT; s0 += NT * SPT) {
        int sbase = s0 + SPT * t;
        if (sbase < SOUT) {
            unsigned long long acc[FPC][SPT];
            #pragma unroll
            for (int fp = 0; fp < FPC; ++fp) {
                float blo = 0.f, bhi = 0.f;
                if (fp < nfp) {
                    int gf = 2 * (fp0 + fp);
                    blo = bias[2 * gp * NF + gf]     + bias[(2 * gp + 1) * NF + gf];
                    bhi = bias[2 * gp * NF + gf + 1] + bias[(2 * gp + 1) * NF + gf + 1];
                }
                unsigned long long pb;
                asm("mov.b64 %0, {%1, %2};" : "=l"(pb)
                    : "r"(__float_as_uint(blo)), "r"(__float_as_uint(bhi)));
                #pragma unroll
                for (int q = 0; q < SPT; ++q) acc[fp][q] = pb;
            }

            int gbase = sbase - (KS - 1);
            #pragma unroll 1
            for (int pc = 0; pc < PCN; ++pc) {
                const float* xr = xb + (long long)pc * SIN;
                unsigned long long xd[WIN];
                #pragma unroll
                for (int i = 0; i < WIN; ++i) {
                    int g = gbase + i;
                    float v = ((unsigned)g < (unsigned)SIN) ? __ldg(&xr[g]) : 0.f;
                    asm("mov.b64 %0, {%1, %1};" : "=l"(xd[i]) : "r"(__float_as_uint(v)));
                }
                const float* wrow = &swT[pc * KS * (2 * FPC)];
                #pragma unroll
                for (int j = 0; j < KS; ++j) {
                    #pragma unroll
                    for (int fp = 0; fp < FPC; ++fp) {
                        unsigned long long wp =
                            *reinterpret_cast<const unsigned long long*>(
                                &wrow[j * (2 * FPC) + 2 * fp]);
                        #pragma unroll
                        for (int q = 0; q < SPT; ++q)
                            asm("fma.rn.f32x2 %0, %1, %2, %0;"
                                : "+l"(acc[fp][q]) : "l"(xd[j + q]), "l"(wp));
                    }
                }
            }

            // store flipped keys, vectorized (pad absorbs tail overflow)
            #pragma unroll
            for (int fp = 0; fp < FPC; ++fp) {
                uint4 klo, khi;
                unsigned lo[SPT], hi[SPT];
                #pragma unroll
                for (int q = 0; q < SPT; ++q) {
                    unsigned l, h;
                    asm("mov.b64 {%0, %1}, %2;" : "=r"(l), "=r"(h) : "l"(acc[fp][q]));
                    lo[q] = flip_key(__uint_as_float(l));
                    hi[q] = flip_key(__uint_as_float(h));
                }
                klo.x = lo[0]; klo.y = lo[1]; klo.z = lo[2]; klo.w = lo[3];
                khi.x = hi[0]; khi.y = hi[1]; khi.z = hi[2]; khi.w = hi[3];
                *reinterpret_cast<uint4*>(&skey[(2 * fp)     * SOUTP + sbase]) = klo;
                *reinterpret_cast<uint4*>(&skey[(2 * fp + 1) * SOUTP + sbase]) = khi;
            }
        }
    }
    __syncthreads();

    // ---- kmax phase: per local channel ------------------------------------
    for (int fl = 0; fl < 2 * nfp; ++fl) {
        const unsigned* keys = &skey[fl * SOUTP];

        if (t == 0) { sh_done = 0; sh_ncand = 0; }
        hist[t] = 0;
        __syncthreads();

        unsigned prefix = 0;
        int krem = KPOOL;

        // pass 1: shift=24 over all SOUT keys
        for (int base = 0; base < SOUT; base += NT) {
            int i = base + t;
            bool ok = (i < SOUT);
            unsigned key = ok ? keys[i] : 0u;
            unsigned ball = __ballot_sync(0xFFFFFFFFu, ok);
            if (ok) {
                int d = (int)(key >> 24);
                unsigned m = __match_any_sync(ball, d);
                if (lane == (__ffs(m) - 1))
                    atomicAdd(&hist[d], __popc(m));
            }
        }
        __syncthreads();
        {   // parallel suffix-scan digit select
            int bb = 255 - t;
            int h = hist[bb];
            int v = h;
            #pragma unroll
            for (int off = 1; off < 32; off <<= 1) {
                int u = __shfl_up_sync(0xFFFFFFFFu, v, off);
                if (lane >= off) v += u;
            }
            if (lane == 31) warpsum[wid] = v;
            __syncthreads();
            if (t < 8) {
                int wv = warpsum[t];
                int vv = wv;
                #pragma unroll
                for (int off = 1; off < 8; off <<= 1) {
                    int u = __shfl_up_sync(0xFFu, vv, off);
                    if (t >= off) vv += u;
                }
                warpsum[t] = vv - wv;
            }
            __syncthreads();
            int suf = v + warpsum[wid];
            int cum = suf - h;
            if (suf >= krem && cum < krem) {
                sh_dig  = (unsigned)bb;
                sh_krem = (unsigned)(krem - cum);
                if (h == krem - cum) sh_done = 1;   // whole bucket kept
            }
            __syncthreads();
        }
        prefix = sh_dig << 24;
        krem   = (int)sh_krem;
        __syncthreads();

        if (!sh_done) {
            // compact candidate indices (order-free; only counts matter)
            unsigned bsel = prefix;
            for (int base = 0; base < SOUT; base += NT) {
                int i = base + t;
                if (i < SOUT && (keys[i] & 0xFF000000u) == bsel) {
                    int pos = atomicAdd(&sh_ncand, 1);
                    cand[pos] = (unsigned short)i;
                }
            }
            __syncthreads();
            int hc = sh_ncand;

            // passes 2..4 over candidates only
            for (int shift = 16; shift >= 0; shift -= 8) {
                if (sh_done) break;   // block-uniform
                hist[t] = 0;
                __syncthreads();
                unsigned hm = 0xFFFFFFFFu << (shift + 8);
                for (int base = 0; base < hc; base += NT) {
                    int ci = base + t;
                    bool ok = false;
                    unsigned key = 0;
                    if (ci < hc) { key = keys[cand[ci]]; ok = ((key & hm) == prefix); }
                    unsigned ball = __ballot_sync(0xFFFFFFFFu, ok);
                    if (ok) {
                        int d = (int)((key >> shift) & 255u);
                        unsigned m = __match_any_sync(ball, d);
                        if (lane == (__ffs(m) - 1))
                            atomicAdd(&hist[d], __popc(m));
                    }
                }
                __syncthreads();
                {
                    int bb = 255 - t;
                    int h = hist[bb];
                    int v = h;
                    #pragma unroll
                    for (int off = 1; off < 32; off <<= 1) {
                        int u = __shfl_up_sync(0xFFFFFFFFu, v, off);
                        if (lane >= off) v += u;
                    }
                    if (lane == 31) warpsum[wid] = v;
                    __syncthreads();
                    if (t < 8) {
                        int wv = warpsum[t];
                        int vv = wv;
                        #pragma unroll
                        for (int off = 1; off < 8; off <<= 1) {
                            int u = __shfl_up_sync(0xFFu, vv, off);
                            if (t >= off) vv += u;
                        }
                        warpsum[t] = vv - wv;
                    }
                    __syncthreads();
                    int suf = v + warpsum[wid];
                    int cum = suf - h;
                    if (suf >= krem && cum < krem) {
                        sh_dig  = (unsigned)bb;
                        sh_krem = (unsigned)(krem - cum);
                        if (h == krem - cum && shift > 0) sh_done = 1;
                    }
                    __syncthreads();
                }
                prefix |= (sh_dig << shift);
                krem = (int)sh_krem;
                __syncthreads();
            }
        }

        int need_eq = sh_done ? (SOUT + 8) : krem;   // sh_done: keep all ==T
        const unsigned T = prefix;
        __syncthreads();

        // stable compaction + tanh -> global pooled row
        long long row = (long long)b * CH_OUT + gp * NF + (2 * fp0 + fl);
        float* yrow = y + row * KPOOL;
        int carry_gt = 0, carry_eq = 0;
        for (int base = 0; base < SOUT; base += NT) {
            int i = base + t;
            unsigned key = 0;
            int gt = 0, eq = 0;
            if (i < SOUT) { key = keys[i]; gt = key > T; eq = key == T; }
            unsigned pk = ((unsigned)gt << 16) | (unsigned)eq;
            unsigned v2 = pk;
            #pragma unroll
            for (int off = 1; off < 32; off <<= 1) {
                unsigned u = __shfl_up_sync(0xFFFFFFFFu, v2, off);
                if (lane >= off) v2 += u;
            }
            if (lane == 31) warpsum[wid] = (int)v2;
            __syncthreads();
            if (t < 8) {
                unsigned wv = (unsigned)warpsum[t];
                unsigned vv = wv;
                #pragma unroll
                for (int off = 1; off < 8; off <<= 1) {
                    unsigned u = __shfl_up_sync(0xFFu, vv, off);
                    if (t >= off) vv += u;
                }
                warpsum[t] = (int)(vv - wv);
                if (t == 7) sh_tot = vv;
            }
            __syncthreads();
            unsigned excl = v2 - pk + (unsigned)warpsum[wid];
            int ggt = carry_gt + (int)(excl >> 16);
            int geq = carry_eq + (int)(excl & 0xFFFFu);
            if (i < SOUT && (gt || (eq && geq < need_eq))) {
                int pos = ggt + min(geq, need_eq);
                float f = (key & 0x80000000u) ? __uint_as_float(key & 0x7FFFFFFFu)
                                              : __uint_as_float(~key);
                yrow[pos] = tanhf(f);
            }
            carry_gt += (int)(sh_tot >> 16);
            carry_eq += (int)(sh_tot & 0xFFFFu);
            __syncthreads();
        }
    }
}

// ---------------------------------------------------------------------------
// 3) Final FC: out[b][n] = fcb[n] + sum_i x[b][i] * fcw[n][i],  i < 352
// ---------------------------------------------------------------------------
__global__ void fc_kernel(const float* __restrict__ x, const float* __restrict__ fcw,
                          const float* __restrict__ fcb, float* __restrict__ out)
{
    int t = blockIdx.x * blockDim.x + threadIdx.x;
    if (t >= 64 * 6) return;
    int b = t / 6, n = t % 6;
    const float* xr = x + b * 352;
    const float* wr = fcw + n * 352;
    float acc = fcb[n];
    #pragma unroll 4
    for (int i = 0; i < 352; ++i) acc = fmaf(xr[i], wr[i], acc);
    out[t] = acc;
}

// ---------------------------------------------------------------------------
extern "C" void kernel_launch(void* const* d_in, const int* in_sizes, int n_in,
                              void* d_out, int out_size)
{
    (void)in_sizes; (void)n_in; (void)out_size;
    const int*   tokens = (const int*)  d_in[0];
    const float* emb    = (const float*)d_in[1];
    const float* w1 = (const float*)d_in[2];
    const float* b1 = (const float*)d_in[3];
    const float* w2 = (const float*)d_in[4];
    const float* b2 = (const float*)d_in[5];
    const float* w3 = (const float*)d_in[6];
    const float* b3 = (const float*)d_in[7];
    const float* w4 = (const float*)d_in[8];
    const float* b4 = (const float*)d_in[9];
    const float* fcw = (const float*)d_in[10];
    const float* fcb = (const float*)d_in[11];
    float* out = (float*)d_out;

    float *B_, *C;
    cudaGetSymbolAddress((void**)&B_, g_bufB);
    cudaGetSymbolAddress((void**)&C,  g_bufC);

    // embed: C = X (64, 64, 1024)
    embed_kernel<<<64 * 16, 256>>>(tokens, emb, C);

    // layer 0: Ghalf=32, SIN=1024, KPOOL=768  -> B_
    conv_kmax_kernel<1, 10, 7, 1024, 768, 2><<<64 * 32 * 2, 256>>>(C, w1, b1, B_, 32);
    // layer 1: Ghalf=16, SIN=768, KPOOL=512   -> C
    conv_kmax_kernel<10, 14, 5, 768, 512, 2><<<64 * 16 * 2, 256>>>(B_, w2, b2, C, 16);
    // layer 2: Ghalf=8, SIN=512, KPOOL=256    -> B_
    conv_kmax_kernel<14, 18, 5, 512, 256, 2><<<64 * 8 * 2, 256>>>(C, w3, b3, B_, 8);
    // layer 3: Ghalf=4, SIN=256, KPOOL=4      -> C
    conv_kmax_kernel<18, 22, 3, 256, 4, 2><<<64 * 4 * 2, 256>>>(B_, w4, b4, C, 4);

    // fc: (64, 352) @ (6, 352)^T + bias -> (64, 6)
    fc_kernel<<<3, 128>>>(C, fcw, fcb, out);
}

// round 11
// speedup vs baseline: 1.6129x; 1.6129x over previous
#include <cuda_runtime.h>
#include <cuda_bf16.h>
#include <math.h>

// ---------------------------------------------------------------------------
// DeepDCNN: emb-gather -> 4x [grouped conv+fold -> warp-level ordered top-k
// + tanh] -> FC.  B=64, SEQ=1024, E=64, NC=6
// Layer i: Ghalf=[32,16,8,4], CING=[1,10,14,18], NF=[10,14,18,22],
//          KS=[7,5,5,3], SOUT=SIN+KS-1, KPOOL=[768,512,256,4]
// ---------------------------------------------------------------------------

__device__ float g_bufA[21094400]; // conv-out (max layer0: 64*320*1030)
__device__ float g_bufB[15728640]; // pooled ping
__device__ float g_bufC[7340032];  // embed / pooled pong

// ---------------------------------------------------------------------------
// 1) Embedding gather + transpose via smem: X[b][e][s] = emb[tokens[b][s]][e]
// ---------------------------------------------------------------------------
__global__ __launch_bounds__(256)
void embed_kernel(const int* __restrict__ tokens,
                  const float* __restrict__ emb,
                  float* __restrict__ X)
{
    __shared__ float sm[64 * 65];
    __shared__ int stok[64];
    int blk = blockIdx.x;            // B * 16 blocks
    int b   = blk >> 4;
    int s0  = (blk & 15) << 6;
    int t   = threadIdx.x;

    if (t < 64) stok[t] = tokens[b * 1024 + s0 + t];
    __syncthreads();

    for (int i = t; i < 64 * 16; i += 256) {
        int r  = i >> 4;
        int c4 = i & 15;
        float4 v = *reinterpret_cast<const float4*>(emb + (long long)stok[r] * 64 + c4 * 4);
        float* d = &sm[r * 65 + c4 * 4];
        d[0] = v.x; d[1] = v.y; d[2] = v.z; d[3] = v.w;
    }
    __syncthreads();

    for (int i = t; i < 64 * 64; i += 256) {
        int e = i >> 6, s = i & 63;
        X[((long long)b * 64 + e) * 1024 + s0 + s] = sm[s * 65 + e];
    }
}

// ---------------------------------------------------------------------------
// 2) Fused grouped conv + bias + fold, packed f32x2 FMA (R6 form).
//    Weights f-innermost in 16B-aligned smem -> broadcast LDS.64.
//    Each thread computes SPT consecutive s positions.
//    NOTE: stiles * THREADS * SPT must cover SOUT (R10 bug: it didn't).
// ---------------------------------------------------------------------------
template<int CING, int NF, int KS, int THREADS, int SPT>
__global__ __launch_bounds__(THREADS)
void conv_fold_kernel(const float* __restrict__ x, const float* __restrict__ w,
                      const float* __restrict__ bias, float* __restrict__ y,
                      int SIN, int SOUT, int Ghalf, int stiles)
{
    constexpr int TS  = THREADS * SPT;
    constexpr int NFP = NF / 2;
    constexpr int WIN = KS + SPT - 1;
    constexpr int PCN = 2 * CING;
    constexpr int WN  = 2 * NF * CING * KS;
    __shared__ __align__(16) float swT[WN];   // [p][c][j][f]

    int bid  = blockIdx.x;
    int tile = bid % stiles;
    int gp   = (bid / stiles) % Ghalf;
    int b    = bid / (stiles * Ghalf);
    int t    = threadIdx.x;
    int s0   = tile * TS;

    const int CH_IN  = Ghalf * 2 * CING;
    const int CH_OUT = Ghalf * NF;

    const float* wg = w + (long long)(2 * gp) * NF * CING * KS;
    for (int e = t; e < WN; e += THREADS) {
        int j  = e % KS;
        int r  = e / KS;
        int c  = r % CING;
        int r2 = r / CING;
        int f  = r2 % NF;
        int p  = r2 / NF;
        swT[((p * CING + c) * KS + j) * NF + f] = wg[e];
    }
    __syncthreads();

    int sbase = s0 + SPT * t;
    if (sbase >= SOUT) return;

    unsigned long long acc[NFP][SPT];
    #pragma unroll
    for (int fp = 0; fp < NFP; ++fp) {
        float blo = bias[2 * gp * NF + 2 * fp]     + bias[(2 * gp + 1) * NF + 2 * fp];
        float bhi = bias[2 * gp * NF + 2 * fp + 1] + bias[(2 * gp + 1) * NF + 2 * fp + 1];
        unsigned long long pb;
        asm("mov.b64 %0, {%1, %2};" : "=l"(pb)
            : "r"(__float_as_uint(blo)), "r"(__float_as_uint(bhi)));
        #pragma unroll
        for (int q = 0; q < SPT; ++q) acc[fp][q] = pb;
    }

    const float* xb = x + (long long)b * CH_IN * SIN + (long long)(2 * gp * CING) * SIN;
    int gbase = sbase - (KS - 1);

    #pragma unroll 1
    for (int pc = 0; pc < PCN; ++pc) {
        const float* xr = xb + (long long)pc * SIN;
        unsigned long long xd[WIN];
        #pragma unroll
        for (int i = 0; i < WIN; ++i) {
            int g = gbase + i;
            float v = ((unsigned)g < (unsigned)SIN) ? __ldg(&xr[g]) : 0.f;
            asm("mov.b64 %0, {%1, %1};" : "=l"(xd[i]) : "r"(__float_as_uint(v)));
        }
        const float* wrow = &swT[pc * KS * NF];
        #pragma unroll
        for (int j = 0; j < KS; ++j) {
            #pragma unroll
            for (int fp = 0; fp < NFP; ++fp) {
                unsigned long long wp =
                    *reinterpret_cast<const unsigned long long*>(&wrow[j * NF + 2 * fp]);
                #pragma unroll
                for (int q = 0; q < SPT; ++q)
                    asm("fma.rn.f32x2 %0, %1, %2, %0;"
                        : "+l"(acc[fp][q]) : "l"(xd[j + q]), "l"(wp));
            }
        }
    }

    float* yb = y + (long long)b * CH_OUT * SOUT + (long long)gp * NF * SOUT;
    #pragma unroll
    for (int fp = 0; fp < NFP; ++fp) {
        #pragma unroll
        for (int q = 0; q < SPT; ++q) {
            int s = sbase + q;
            if (s < SOUT) {
                unsigned lo, hi;
                asm("mov.b64 {%0, %1}, %2;" : "=r"(lo), "=r"(hi) : "l"(acc[fp][q]));
                yb[(long long)(2 * fp)     * SOUT + s] = __uint_as_float(lo);
                yb[(long long)(2 * fp + 1) * SOUT + s] = __uint_as_float(hi);
            }
        }
    }
}

// ---------------------------------------------------------------------------
// 3) WARP-LEVEL ordered top-k + tanh. One warp per row, 8 warps/block, no
//    __syncthreads. Radix select (MSB-first 8-bit) with per-warp smem hist
//    (warp-aggregated atomics), 8-bins-per-lane suffix digit select, ballot
//    candidate compaction, ballot stable compaction keeping keys > T plus
//    first need_eq keys == T (lax.top_k tie order).
// ---------------------------------------------------------------------------
__device__ __forceinline__ unsigned flip_key(float f) {
    unsigned u = __float_as_uint(f);
    return (u & 0x80000000u) ? ~u : (u | 0x80000000u);
}

// warp digit select: returns (dig, krem_new, bucket_count) broadcast to all
__device__ __forceinline__ void warp_select_digit(const int* h, int lane, int krem,
                                                  int& dig, int& krem_new, int& bcnt)
{
    int csum = 0;
    int hb_[8];
    #pragma unroll
    for (int j = 0; j < 8; ++j) { hb_[j] = h[lane * 8 + j]; csum += hb_[j]; }
    // suffix over lanes (higher lane = higher bins)
    int S = csum;
    #pragma unroll
    for (int off = 1; off < 32; off <<= 1) {
        int u = __shfl_down_sync(0xFFFFFFFFu, S, off);
        if (lane + off < 32) S += u;
    }
    int ab = S - csum;   // count in bins above my chunk
    int found = -1, kn = 0, bc = 0;
    #pragma unroll
    for (int j = 7; j >= 0; --j) {
        int hb = hb_[j];
        if (found < 0 && ab + hb >= krem && ab < krem) {
            found = lane * 8 + j; kn = krem - ab; bc = hb;
        }
        ab += hb;
    }
    unsigned fb = __ballot_sync(0xFFFFFFFFu, found >= 0);
    int src = __ffs(fb) - 1;
    dig      = __shfl_sync(0xFFFFFFFFu, found, src);
    krem_new = __shfl_sync(0xFFFFFFFFu, kn, src);
    bcnt     = __shfl_sync(0xFFFFFFFFu, bc, src);
}

__global__ __launch_bounds__(256)
void kmax_warp_kernel(const float* __restrict__ x, float* __restrict__ y,
                      int n, int k, int nrows)
{
    __shared__ int hist[8][256];
    __shared__ unsigned short cand[8][1032];

    int wid  = threadIdx.x >> 5;
    int lane = threadIdx.x & 31;
    int row  = blockIdx.x * 8 + wid;
    if (row >= nrows) return;                 // warp-uniform

    const float* xr = x + (long long)row * n;
    int* h = hist[wid];
    unsigned short* cd = cand[wid];

    // ---- pass 1: hist of top byte over all n keys -------------------------
    #pragma unroll
    for (int j = 0; j < 8; ++j) h[lane + 32 * j] = 0;
    __syncwarp();
    for (int base = 0; base < n; base += 128) {
        unsigned kv[4]; bool okv[4];
        #pragma unroll
        for (int u2 = 0; u2 < 4; ++u2) {
            int i = base + u2 * 32 + lane;
            okv[u2] = (i < n);
            kv[u2]  = okv[u2] ? flip_key(__ldg(&xr[i])) : 0u;
        }
        #pragma unroll
        for (int u2 = 0; u2 < 4; ++u2) {
            unsigned ball = __ballot_sync(0xFFFFFFFFu, okv[u2]);
            if (okv[u2]) {
                int d = (int)(kv[u2] >> 24);
                unsigned m = __match_any_sync(ball, d);
                if (lane == (__ffs(m) - 1)) atomicAdd(&h[d], __popc(m));
            }
        }
    }
    __syncwarp();

    int dig, krem, bcnt;
    warp_select_digit(h, lane, k, dig, krem, bcnt);
    unsigned prefix = (unsigned)dig << 24;
    int done = (bcnt == krem);                // whole bucket kept

    if (!done) {
        // ---- compact candidate indices (stable, ballot prefix) ------------
        int hc = 0;
        for (int base = 0; base < n; base += 128) {
            bool mv[4];
            #pragma unroll
            for (int u2 = 0; u2 < 4; ++u2) {
                int i = base + u2 * 32 + lane;
                mv[u2] = (i < n) && ((flip_key(__ldg(&xr[i])) >> 24) == (unsigned)dig);
            }
            #pragma unroll
            for (int u2 = 0; u2 < 4; ++u2) {
                unsigned ball = __ballot_sync(0xFFFFFFFFu, mv[u2]);
                if (mv[u2]) {
                    int pos = hc + __popc(ball & ((1u << lane) - 1));
                    cd[pos] = (unsigned short)(base + u2 * 32 + lane);
                }
                hc += __popc(ball);
            }
        }
        __syncwarp();

        // ---- refinement passes over candidates only ------------------------
        for (int shift = 16; shift >= 0; shift -= 8) {
            if (done) break;                  // warp-uniform
            #pragma unroll
            for (int j = 0; j < 8; ++j) h[lane + 32 * j] = 0;
            __syncwarp();
            unsigned hm = 0xFFFFFFFFu << (shift + 8);
            for (int base = 0; base < hc; base += 32) {
                int ci = base + lane;
                bool ok = false; unsigned key = 0;
                if (ci < hc) {
                    key = flip_key(__ldg(&xr[cd[ci]]));
                    ok  = ((key & hm) == prefix);
                }
                unsigned ball = __ballot_sync(0xFFFFFFFFu, ok);
                if (ok) {
                    int d = (int)((key >> shift) & 255u);
                    unsigned m = __match_any_sync(ball, d);
                    if (lane == (__ffs(m) - 1)) atomicAdd(&h[d], __popc(m));
                }
            }
            __syncwarp();
            int kn2;
            warp_select_digit(h, lane, krem, dig, kn2, bcnt);
            prefix |= ((unsigned)dig << shift);
            krem = kn2;
            if (bcnt == krem && shift > 0) done = 1;
        }
    }

    const unsigned T = prefix;
    const int need_eq = done ? (n + 8) : krem;

    // ---- stable compaction + tanh ----------------------------------------
    float* yrow = y + (long long)row * k;
    int carry_gt = 0, carry_eq = 0;
    for (int base = 0; base < n; base += 128) {
        unsigned kv[4]; bool okv[4];
        #pragma unroll
        for (int u2 = 0; u2 < 4; ++u2) {
            int i = base + u2 * 32 + lane;
            okv[u2] = (i < n);
            kv[u2]  = okv[u2] ? flip_key(__ldg(&xr[i])) : 0u;
        }
        #pragma unroll
        for (int u2 = 0; u2 < 4; ++u2) {
            bool gt = okv[u2] && (kv[u2] > T);
            bool eq = okv[u2] && (kv[u2] == T);
            unsigned bg = __ballot_sync(0xFFFFFFFFu, gt);
            unsigned be = __ballot_sync(0xFFFFFFFFu, eq);
            unsigned ltm = (1u << lane) - 1;
            int ggt = carry_gt + __popc(bg & ltm);
            int geq = carry_eq + __popc(be & ltm);
            if (gt || (eq && geq < need_eq)) {
                int pos = ggt + min(geq, need_eq);
                unsigned key = kv[u2];
                float f = (key & 0x80000000u) ? __uint_as_float(key & 0x7FFFFFFFu)
                                              : __uint_as_float(~key);
                yrow[pos] = tanhf(f);
            }
            carry_gt += __popc(bg);
            carry_eq += __popc(be);
        }
    }
}

// ---------------------------------------------------------------------------
// 4) Final FC: out[b][n] = fcb[n] + sum_i x[b][i] * fcw[n][i],  i < 352
// ---------------------------------------------------------------------------
__global__ void fc_kernel(const float* __restrict__ x, const float* __restrict__ fcw,
                          const float* __restrict__ fcb, float* __restrict__ out)
{
    int t = blockIdx.x * blockDim.x + threadIdx.x;
    if (t >= 64 * 6) return;
    int b = t / 6, n = t % 6;
    const float* xr = x + b * 352;
    const float* wr = fcw + n * 352;
    float acc = fcb[n];
    #pragma unroll 4
    for (int i = 0; i < 352; ++i) acc = fmaf(xr[i], wr[i], acc);
    out[t] = acc;
}

// ---------------------------------------------------------------------------
extern "C" void kernel_launch(void* const* d_in, const int* in_sizes, int n_in,
                              void* d_out, int out_size)
{
    (void)in_sizes; (void)n_in; (void)out_size;
    const int*   tokens = (const int*)  d_in[0];
    const float* emb    = (const float*)d_in[1];
    const float* w1 = (const float*)d_in[2];
    const float* b1 = (const float*)d_in[3];
    const float* w2 = (const float*)d_in[4];
    const float* b2 = (const float*)d_in[5];
    const float* w3 = (const float*)d_in[6];
    const float* b3 = (const float*)d_in[7];
    const float* w4 = (const float*)d_in[8];
    const float* b4 = (const float*)d_in[9];
    const float* fcw = (const float*)d_in[10];
    const float* fcb = (const float*)d_in[11];
    float* out = (float*)d_out;

    float *A, *B_, *C;
    cudaGetSymbolAddress((void**)&A,  g_bufA);
    cudaGetSymbolAddress((void**)&B_, g_bufB);
    cudaGetSymbolAddress((void**)&C,  g_bufC);

    // embed: C = X (64, 64, 1024)
    embed_kernel<<<64 * 16, 256>>>(tokens, emb, C);

    // layer 0: Sin 1024 -> SOUT 1030, TS=512, stiles=3 (1536 >= 1030) ✓
    conv_fold_kernel<1, 10, 7, 128, 4><<<64 * 32 * 3, 128>>>(C, w1, b1, A, 1024, 1030, 32, 3);
    kmax_warp_kernel<<<(20480 + 7) / 8, 256>>>(A, B_, 1030, 768, 20480);

    // layer 1: Sin 768 -> SOUT 772, TS=512, stiles=2 (1024 >= 772) ✓
    conv_fold_kernel<10, 14, 5, 128, 4><<<64 * 16 * 2, 128>>>(B_, w2, b2, A, 768, 772, 16, 2);
    kmax_warp_kernel<<<(14336 + 7) / 8, 256>>>(A, C, 772, 512, 14336);

    // layer 2: Sin 512 -> SOUT 516, TS=256, stiles=3 (768 >= 516) ✓ (R10 bug: was 2)
    conv_fold_kernel<14, 18, 5, 128, 2><<<64 * 8 * 3, 128>>>(C, w3, b3, A, 512, 516, 8, 3);
    kmax_warp_kernel<<<(9216 + 7) / 8, 256>>>(A, B_, 516, 256, 9216);

    // layer 3: Sin 256 -> SOUT 258, TS=256, stiles=2 (512 >= 258) ✓ (R10 bug: was 1)
    conv_fold_kernel<18, 22, 3, 128, 2><<<64 * 4 * 2, 128>>>(B_, w4, b4, A, 256, 258, 4, 2);
    kmax_warp_kernel<<<(5632 + 7) / 8, 256>>>(A, C, 258, 4, 5632);

    // fc: (64, 352) @ (6, 352)^T + bias -> (64, 6)
    fc_kernel<<<3, 128>>>(C, fcw, fcb, out);
}